// round 1
// baseline (speedup 1.0000x reference)
#include <cuda_runtime.h>
#include <cstdint>

#define NNODES 512
#define FDIM   64
#define EMAX   16384

// Scratch (static __device__ globals — no runtime allocation)
__device__ int   g_M [NNODES * NNODES];    // edge id at (i,j), -1 if none
__device__ int   g_MT[NNODES * NNODES];    // transposed copy
__device__ float g_X  [EMAX * FDIM];       // C @ W_L1^T
__device__ float g_Y  [EMAX * FDIM];       // C @ W_L2^T
__device__ float g_tmp[EMAX * 2 * FDIM];   // [C | tmp_matmul]
__device__ float g_H  [EMAX * 8 * FDIM];   // relu(tmp @ W_mlp1^T), 16384x512

// ---------------------------------------------------------------------------
__global__ void k_init() {
    int i = blockIdx.x * blockDim.x + threadIdx.x;
    if (i < NNODES * NNODES) { g_M[i] = -1; g_MT[i] = -1; }
}

__global__ void k_scatter(const int* __restrict__ ei, int E) {
    int e = blockIdx.x * blockDim.x + threadIdx.x;
    if (e < E) {
        int i = ei[e];
        int k = ei[E + e];
        g_M [i * NNODES + k] = e;
        g_MT[k * NNODES + i] = e;
    }
}

// ---------------------------------------------------------------------------
// X = C @ W1^T, Y = C @ W2^T, and tmp[:, :64] = C.  8 edges per block.
__global__ void k_xy(const float* __restrict__ C,
                     const float* __restrict__ W1,
                     const float* __restrict__ W2) {
    __shared__ float ws1[64 * 65];
    __shared__ float ws2[64 * 65];
    __shared__ float cs [8 * 64];
    int t = threadIdx.x;                       // 256 threads
    #pragma unroll
    for (int i = 0; i < 16; i++) {
        int idx = t + i * 256;                 // 0..4095
        int f = idx >> 6, k = idx & 63;
        ws1[f * 65 + k] = W1[idx];
        ws2[f * 65 + k] = W2[idx];
    }
    int e0 = blockIdx.x * 8;
    #pragma unroll
    for (int i = 0; i < 2; i++) {
        int idx = t + i * 256;
        cs[idx] = C[e0 * 64 + idx];
    }
    __syncthreads();
    #pragma unroll
    for (int i = 0; i < 2; i++) {              // copy C into tmp[:, :64]
        int idx = t + i * 256;
        int e = idx >> 6, f = idx & 63;
        g_tmp[(e0 + e) * 128 + f] = cs[idx];
    }
    #pragma unroll
    for (int i = 0; i < 2; i++) {
        int idx = t + i * 256;
        int e = idx >> 6, f = idx & 63;
        const float* cr = &cs[e * 64];
        float ax = 0.f, ay = 0.f;
        #pragma unroll
        for (int k = 0; k < 64; k++) {
            float c = cr[k];
            ax = fmaf(ws1[f * 65 + k], c, ax);
            ay = fmaf(ws2[f * 65 + k], c, ay);
        }
        g_X[(e0 + e) * 64 + f] = ax;
        g_Y[(e0 + e) * 64 + f] = ay;
    }
}

// ---------------------------------------------------------------------------
// Sparse-sparse path contraction: for output edge e=(i,k),
//   tmp[e, 64+f] = sum_j X[M[i,j], f] * Y[M[j,k], f]
// One block (64 threads) per edge; phase 1 builds match list, phase 2 FMAs.
__global__ void k_paths(const int* __restrict__ ei) {
    __shared__ int2 pairs[NNODES];
    __shared__ int  cnt;
    int e = blockIdx.x;
    int t = threadIdx.x;                       // 64 threads
    int i = ei[e];
    int k = ei[gridDim.x + e];
    if (t == 0) cnt = 0;
    __syncthreads();
    const int* rowM  = &g_M [i * NNODES];
    const int* rowMT = &g_MT[k * NNODES];
    #pragma unroll
    for (int jj = 0; jj < NNODES / 64; jj++) {
        int j = t + jj * 64;
        int e1 = rowM[j];
        int e2 = rowMT[j];
        if (e1 >= 0 && e2 >= 0) {
            int p = atomicAdd(&cnt, 1);
            pairs[p] = make_int2(e1, e2);
        }
    }
    __syncthreads();
    int n = cnt;
    float acc = 0.f;
    for (int p = 0; p < n; p++) {
        int2 pr = pairs[p];
        acc = fmaf(g_X[pr.x * 64 + t], g_Y[pr.y * 64 + t], acc);
    }
    g_tmp[e * 128 + 64 + t] = acc;
}

// ---------------------------------------------------------------------------
// C[m,n] = act( sum_k A[m,k] * B[n,k] ).  A: MxK row-major, B: NxK row-major.
// BM=BN=64, BK=16, 256 threads, 4x4 micro-tile. M,N,K multiples of tile sizes.
template <bool RELU>
__global__ void gemm_tn(const float* __restrict__ A,
                        const float* __restrict__ B,
                        float* __restrict__ Cout,
                        int M, int N, int K) {
    __shared__ float As[16][65];   // [k][m]
    __shared__ float Bs[16][65];   // [k][n]
    int bm = blockIdx.y * 64;
    int bn = blockIdx.x * 64;
    int tid = threadIdx.x;
    int tx = tid & 15, ty = tid >> 4;
    float acc[4][4] = {};
    for (int k0 = 0; k0 < K; k0 += 16) {
        #pragma unroll
        for (int i = 0; i < 4; i++) {
            int idx = tid + i * 256;           // 0..1023
            int r = idx >> 4, c = idx & 15;
            As[c][r] = A[(bm + r) * K + k0 + c];
            Bs[c][r] = B[(bn + r) * K + k0 + c];
        }
        __syncthreads();
        #pragma unroll
        for (int kk = 0; kk < 16; kk++) {
            float a[4], b[4];
            #pragma unroll
            for (int i = 0; i < 4; i++) a[i] = As[kk][ty * 4 + i];
            #pragma unroll
            for (int j = 0; j < 4; j++) b[j] = Bs[kk][tx * 4 + j];
            #pragma unroll
            for (int i = 0; i < 4; i++)
                #pragma unroll
                for (int j = 0; j < 4; j++)
                    acc[i][j] = fmaf(a[i], b[j], acc[i][j]);
        }
        __syncthreads();
    }
    #pragma unroll
    for (int i = 0; i < 4; i++)
        #pragma unroll
        for (int j = 0; j < 4; j++) {
            float v = acc[i][j];
            if (RELU) v = fmaxf(v, 0.f);
            Cout[(bm + ty * 4 + i) * N + bn + tx * 4 + j] = v;
        }
}

// ---------------------------------------------------------------------------
extern "C" void kernel_launch(void* const* d_in, const int* in_sizes, int n_in,
                              void* d_out, int out_size) {
    const int*   edge_index = (const int*)  d_in[0];   // [2, E]
    const float* C          = (const float*)d_in[1];   // [E, 64]
    // d_in[2] = batch_node (unused by the reference computation)
    const float* W_L1       = (const float*)d_in[3];   // [64, 64]
    const float* W_L2       = (const float*)d_in[4];   // [64, 64]
    const float* W_mlp1     = (const float*)d_in[5];   // [512, 128]
    const float* W_mlp2     = (const float*)d_in[6];   // [64, 512]
    float* out = (float*)d_out;                        // [E, 64]

    int E = in_sizes[0] / 2;                           // 16384

    float* pX;   cudaGetSymbolAddress((void**)&pX,   g_X);
    float* pH;   cudaGetSymbolAddress((void**)&pH,   g_H);
    float* ptmp; cudaGetSymbolAddress((void**)&ptmp, g_tmp);
    float* pW2sc; // reuse pointer fetch for B operand of gemm2 (it's W_mlp2, input)
    (void)pW2sc;

    // 1. reset edge-id matrices
    k_init<<<(NNODES * NNODES + 255) / 256, 256>>>();
    // 2. scatter edge ids
    k_scatter<<<(E + 255) / 256, 256>>>(edge_index, E);
    // 3. X = C@W1^T, Y = C@W2^T, tmp[:, :64] = C
    k_xy<<<E / 8, 256>>>(C, W_L1, W_L2);
    // 4. sparse path contraction -> tmp[:, 64:128]
    k_paths<<<E, 64>>>(edge_index);
    // 5. H = relu(tmp @ W_mlp1^T)   [E,128]x[512,128] -> [E,512]
    {
        dim3 grid(512 / 64, E / 64);
        gemm_tn<true><<<grid, 256>>>(ptmp, W_mlp1, pH, E, 512, 128);
    }
    // 6. out = H @ W_mlp2^T          [E,512]x[64,512] -> [E,64]
    {
        dim3 grid(64 / 64, E / 64);
        gemm_tn<false><<<grid, 256>>>(pH, W_mlp2, out, E, 64, 512);
    }
}

// round 3
// speedup vs baseline: 2.3498x; 2.3498x over previous
#include <cuda_runtime.h>
#include <cuda_bf16.h>
#include <cstdint>

#define NNODES 512
#define FDIM   64
#define EMAX   16384

// ---------------------------------------------------------------------------
// Scratch (static __device__ globals — no runtime allocation)
__device__ __align__(16) int   g_M [NNODES * NNODES];
__device__ __align__(16) int   g_MT[NNODES * NNODES];
__device__ __align__(16) float g_X  [EMAX * FDIM];
__device__ __align__(16) float g_Y  [EMAX * FDIM];
__device__ __align__(16) float g_tmp[EMAX * 2 * FDIM];  // [C | tmp_matmul]

// ---------------------------------------------------------------------------
__device__ __forceinline__ uint32_t smem_u32(const void* p) {
    uint32_t a;
    asm("{ .reg .u64 t; cvta.to.shared.u64 t, %1; cvt.u32.u64 %0, t; }" : "=r"(a) : "l"(p));
    return a;
}

// mma.sync m16n8k16 row.col bf16 -> f32 accumulate (PTX baseline, sm_80+)
__device__ __forceinline__ void mma16816(float* c, uint32_t a0, uint32_t a1,
                                         uint32_t a2, uint32_t a3,
                                         uint32_t b0, uint32_t b1) {
    asm("mma.sync.aligned.m16n8k16.row.col.f32.bf16.bf16.f32 "
        "{%0,%1,%2,%3}, {%4,%5,%6,%7}, {%8,%9}, {%0,%1,%2,%3};"
        : "+f"(c[0]), "+f"(c[1]), "+f"(c[2]), "+f"(c[3])
        : "r"(a0), "r"(a1), "r"(a2), "r"(a3), "r"(b0), "r"(b1));
}

__device__ __forceinline__ void ldmx4(uint32_t* r, uint32_t addr) {
    asm volatile("ldmatrix.sync.aligned.m8n8.x4.shared.b16 {%0,%1,%2,%3}, [%4];"
                 : "=r"(r[0]), "=r"(r[1]), "=r"(r[2]), "=r"(r[3]) : "r"(addr));
}

__device__ __forceinline__ uint32_t packbf(float x, float y) {
    __nv_bfloat162 t = __floats2bfloat162_rn(x, y);
    return *reinterpret_cast<uint32_t*>(&t);
}

// ---------------------------------------------------------------------------
__global__ void k_init() {
    int i = blockIdx.x * blockDim.x + threadIdx.x;
    if (i < NNODES * NNODES) { g_M[i] = -1; g_MT[i] = -1; }
}

__global__ void k_scatter(const int* __restrict__ ei, int E) {
    int e = blockIdx.x * blockDim.x + threadIdx.x;
    if (e < E) {
        int i = ei[e];
        int k = ei[E + e];
        g_M [i * NNODES + k] = e;
        g_MT[k * NNODES + i] = e;
    }
}

// ---------------------------------------------------------------------------
// X = C @ W1^T, Y = C @ W2^T, and tmp[:, :64] = C.  8 edges per block.
__global__ void k_xy(const float* __restrict__ C,
                     const float* __restrict__ W1,
                     const float* __restrict__ W2) {
    __shared__ float ws1[64 * 65];
    __shared__ float ws2[64 * 65];
    __shared__ float cs [8 * 64];
    int t = threadIdx.x;                       // 256 threads
    #pragma unroll
    for (int i = 0; i < 16; i++) {
        int idx = t + i * 256;
        int f = idx >> 6, k = idx & 63;
        ws1[f * 65 + k] = W1[idx];
        ws2[f * 65 + k] = W2[idx];
    }
    int e0 = blockIdx.x * 8;
    #pragma unroll
    for (int i = 0; i < 2; i++) {
        int idx = t + i * 256;
        cs[idx] = C[e0 * 64 + idx];
    }
    __syncthreads();
    #pragma unroll
    for (int i = 0; i < 2; i++) {
        int idx = t + i * 256;
        int e = idx >> 6, f = idx & 63;
        g_tmp[(e0 + e) * 128 + f] = cs[idx];
    }
    #pragma unroll
    for (int i = 0; i < 2; i++) {
        int idx = t + i * 256;
        int e = idx >> 6, f = idx & 63;
        const float* cr = &cs[e * 64];
        float ax = 0.f, ay = 0.f;
        #pragma unroll
        for (int k = 0; k < 64; k++) {
            float c = cr[k];
            ax = fmaf(ws1[f * 65 + k], c, ax);
            ay = fmaf(ws2[f * 65 + k], c, ay);
        }
        g_X[(e0 + e) * 64 + f] = ax;
        g_Y[(e0 + e) * 64 + f] = ay;
    }
}

// ---------------------------------------------------------------------------
// Sparse path contraction.
__global__ void k_paths(const int* __restrict__ ei) {
    __shared__ int2 pairs[NNODES];
    __shared__ int  cnt;
    int e = blockIdx.x;
    int t = threadIdx.x;                       // 64 threads
    int i = ei[e];
    int k = ei[gridDim.x + e];
    if (t == 0) cnt = 0;
    __syncthreads();
    const int* rowM  = &g_M [i * NNODES];
    const int* rowMT = &g_MT[k * NNODES];
    #pragma unroll
    for (int jj = 0; jj < NNODES / 64; jj++) {
        int j = t + jj * 64;
        int e1 = rowM[j];
        int e2 = rowMT[j];
        if (e1 >= 0 && e2 >= 0) {
            int p = atomicAdd(&cnt, 1);
            pairs[p] = make_int2(e1, e2);
        }
    }
    __syncthreads();
    int n = cnt;
    float acc = 0.f;
    for (int p = 0; p < n; p++) {
        int2 pr = pairs[p];
        acc = fmaf(g_X[pr.x * 64 + t], g_Y[pr.y * 64 + t], acc);
    }
    g_tmp[e * 128 + 64 + t] = acc;
}

// ---------------------------------------------------------------------------
// Fused MLP via mma.sync (bf16x3 split, fp32 accum in registers).
// CTA = 128 edge rows, 256 threads = 8 warps x 16 rows.
// out[128,64] = relu(tmp[128,128] @ W1^T) @ W2^T, N of GEMM1 in 4 chunks of 128.
// H stays in registers: GEMM1 C-fragments == GEMM2 A-fragments layout.
//
// SMEM tile layout (bf16): row stride 256B (128 elems);
// phys(r, kbyte) = r*256 + (kbyte ^ ((r&7)<<4))   (conflict-free for ldmatrix)

#define OFF_AHI 0u
#define OFF_ALO 32768u
#define OFF_BHI 65536u
#define OFF_BLO 98304u
#define SMEM_TOT 131072u

__device__ __forceinline__ void stage_tile(char* smem, uint32_t hiOff, uint32_t loOff,
                                           const float4* src, int nfloat4, int tid) {
    for (int i = tid; i < nfloat4; i += 256) {
        float4 v = src[i];
        int r = i >> 5;
        int kb = (i & 31) * 16;               // byte offset of 4 bf16 pairs... (4 floats -> 8 bytes bf16)
        // 4 floats -> 4 bf16 = 8 bytes at element offset (i&31)*4 -> byte (i&31)*8
        kb = (i & 31) * 8;
        __nv_bfloat16 h0 = __float2bfloat16(v.x), h1 = __float2bfloat16(v.y);
        __nv_bfloat16 h2 = __float2bfloat16(v.z), h3 = __float2bfloat16(v.w);
        float l0 = v.x - __bfloat162float(h0), l1 = v.y - __bfloat162float(h1);
        float l2 = v.z - __bfloat162float(h2), l3 = v.w - __bfloat162float(h3);
        uint32_t hw0 = packbf(__bfloat162float(h0), __bfloat162float(h1));
        uint32_t hw1 = packbf(__bfloat162float(h2), __bfloat162float(h3));
        uint32_t lw0 = packbf(l0, l1);
        uint32_t lw1 = packbf(l2, l3);
        uint32_t phys = (uint32_t)r * 256u + ((uint32_t)kb ^ (((uint32_t)r & 7u) << 4));
        *(uint2*)(smem + hiOff + phys) = make_uint2(hw0, hw1);
        *(uint2*)(smem + loOff + phys) = make_uint2(lw0, lw1);
    }
}

__global__ __launch_bounds__(256, 1)
void k_mlp(const float* __restrict__ W1,   // [512,128]
           const float* __restrict__ W2,   // [64,512]
           float* __restrict__ out) {      // [E,64]
    extern __shared__ char smem[];
    uint32_t sb = smem_u32(smem);
    int tid = threadIdx.x;
    int wid = tid >> 5, lane = tid & 31;
    int e0 = blockIdx.x * 128;
    int rw = wid * 16;

    // ldmatrix x4 per-lane address components
    int l7 = lane & 7;
    int sel = lane >> 3;                       // 0..3
    uint32_t xorv = (uint32_t)l7 << 4;

    // A-frag addr: tiles {r0 k0, r8 k0, r0 k1, r8 k1} -> sel bit0=row+8, bit1=k+16B
    uint32_t aRow = (uint32_t)(rw + (sel & 1) * 8 + l7) * 256u;
    uint32_t aKof = (uint32_t)(sel >> 1) * 16u;
    // B-frag addr: tiles {n0 k0, n0 k1, n8 k0, n8 k1} -> sel bit1=n+8, bit0=k+16B
    uint32_t bRowBase = (uint32_t)((sel >> 1) * 8 + l7) * 256u;
    uint32_t bKof = (uint32_t)(sel & 1) * 16u;

    float d2a[8][4];
    #pragma unroll
    for (int i = 0; i < 8; i++)
        #pragma unroll
        for (int j = 0; j < 4; j++) d2a[i][j] = 0.f;

    // Stage A = tmp[e0:e0+128, 0:128]
    stage_tile(smem, OFF_AHI, OFF_ALO, (const float4*)g_tmp + (size_t)e0 * 32, 4096, tid);

    for (int c = 0; c < 4; c++) {
        __syncthreads();   // previous chunk's B2 reads done (and A staged, iter 0)
        // Stage B1 = W1 rows [c*128, c*128+128)  (contiguous 64KB)
        stage_tile(smem, OFF_BHI, OFF_BLO, (const float4*)W1 + c * 4096, 4096, tid);
        __syncthreads();

        float d1[16][4];
        #pragma unroll
        for (int i = 0; i < 16; i++)
            #pragma unroll
            for (int j = 0; j < 4; j++) d1[i][j] = 0.f;

        // MMA1: d1[16 tiles of n8] += A[128,128] @ B1^T, 3 bf16 passes
        #pragma unroll
        for (int p = 0; p < 3; p++) {
            uint32_t abase = sb + (p == 2 ? OFF_ALO : OFF_AHI);
            uint32_t bbase = sb + (p == 1 ? OFF_BLO : OFF_BHI);
            #pragma unroll
            for (int ks = 0; ks < 8; ks++) {
                uint32_t kb = (uint32_t)ks * 32u;
                uint32_t a[4];
                ldmx4(a, abase + aRow + ((kb + aKof) ^ xorv));
                #pragma unroll
                for (int np = 0; np < 8; np++) {
                    uint32_t b[4];
                    ldmx4(b, bbase + (uint32_t)np * 4096u + bRowBase + ((kb + bKof) ^ xorv));
                    mma16816(d1[2 * np],     a[0], a[1], a[2], a[3], b[0], b[1]);
                    mma16816(d1[2 * np + 1], a[0], a[1], a[2], a[3], b[2], b[3]);
                }
            }
        }

        __syncthreads();   // MMA1 B reads done before overwrite
        // Stage B2 = W2[0:64, c*128 : c*128+128)
        {
            for (int i = tid; i < 2048; i += 256) {
                int r = i >> 5;
                int k4 = (i & 31) * 4;
                float4 v = *(const float4*)(W2 + r * 512 + c * 128 + k4);
                int kb = (i & 31) * 8;
                __nv_bfloat16 h0 = __float2bfloat16(v.x), h1 = __float2bfloat16(v.y);
                __nv_bfloat16 h2 = __float2bfloat16(v.z), h3 = __float2bfloat16(v.w);
                float l0 = v.x - __bfloat162float(h0), l1 = v.y - __bfloat162float(h1);
                float l2 = v.z - __bfloat162float(h2), l3 = v.w - __bfloat162float(h3);
                uint32_t phys = (uint32_t)r * 256u + ((uint32_t)kb ^ (((uint32_t)r & 7u) << 4));
                *(uint2*)(smem + OFF_BHI + phys) =
                    make_uint2(packbf(__bfloat162float(h0), __bfloat162float(h1)),
                               packbf(__bfloat162float(h2), __bfloat162float(h3)));
                *(uint2*)(smem + OFF_BLO + phys) = make_uint2(packbf(l0, l1), packbf(l2, l3));
            }
        }
        __syncthreads();

        // MMA2: d2a[8 tiles of n8] += relu(d1) @ B2^T
        // A-frags built from d1 (C-fragment layout == A-fragment layout).
        #pragma unroll
        for (int kt = 0; kt < 8; kt++) {
            float va0 = fmaxf(d1[2 * kt][0], 0.f), va1 = fmaxf(d1[2 * kt][1], 0.f);
            float va2 = fmaxf(d1[2 * kt][2], 0.f), va3 = fmaxf(d1[2 * kt][3], 0.f);
            float vb0 = fmaxf(d1[2 * kt + 1][0], 0.f), vb1 = fmaxf(d1[2 * kt + 1][1], 0.f);
            float vb2 = fmaxf(d1[2 * kt + 1][2], 0.f), vb3 = fmaxf(d1[2 * kt + 1][3], 0.f);
            float ha0 = __bfloat162float(__float2bfloat16(va0));
            float ha1 = __bfloat162float(__float2bfloat16(va1));
            float ha2 = __bfloat162float(__float2bfloat16(va2));
            float ha3 = __bfloat162float(__float2bfloat16(va3));
            float hb0 = __bfloat162float(__float2bfloat16(vb0));
            float hb1 = __bfloat162float(__float2bfloat16(vb1));
            float hb2 = __bfloat162float(__float2bfloat16(vb2));
            float hb3 = __bfloat162float(__float2bfloat16(vb3));
            uint32_t ah[4] = { packbf(ha0, ha1), packbf(ha2, ha3),
                               packbf(hb0, hb1), packbf(hb2, hb3) };
            uint32_t al[4] = { packbf(va0 - ha0, va1 - ha1), packbf(va2 - ha2, va3 - ha3),
                               packbf(vb0 - hb0, vb1 - hb1), packbf(vb2 - hb2, vb3 - hb3) };
            uint32_t kb = (uint32_t)kt * 32u;
            #pragma unroll
            for (int np = 0; np < 4; np++) {
                uint32_t bh[4], bl[4];
                uint32_t off = (uint32_t)np * 4096u + bRowBase + ((kb + bKof) ^ xorv);
                ldmx4(bh, sb + OFF_BHI + off);
                ldmx4(bl, sb + OFF_BLO + off);
                mma16816(d2a[2 * np],     ah[0], ah[1], ah[2], ah[3], bh[0], bh[1]);
                mma16816(d2a[2 * np + 1], ah[0], ah[1], ah[2], ah[3], bh[2], bh[3]);
                mma16816(d2a[2 * np],     ah[0], ah[1], ah[2], ah[3], bl[0], bl[1]);
                mma16816(d2a[2 * np + 1], ah[0], ah[1], ah[2], ah[3], bl[2], bl[3]);
                mma16816(d2a[2 * np],     al[0], al[1], al[2], al[3], bh[0], bh[1]);
                mma16816(d2a[2 * np + 1], al[0], al[1], al[2], al[3], bh[2], bh[3]);
            }
        }
    }

    // Write out: warp rows rw + lane/4 (+8), cols nt*8 + (lane%4)*2
    int r0 = e0 + rw + (lane >> 2);
    int c0 = (lane & 3) * 2;
    #pragma unroll
    for (int nt = 0; nt < 8; nt++) {
        *(float2*)(out + (size_t)r0 * 64 + nt * 8 + c0)       = make_float2(d2a[nt][0], d2a[nt][1]);
        *(float2*)(out + (size_t)(r0 + 8) * 64 + nt * 8 + c0) = make_float2(d2a[nt][2], d2a[nt][3]);
    }
}

// ---------------------------------------------------------------------------
extern "C" void kernel_launch(void* const* d_in, const int* in_sizes, int n_in,
                              void* d_out, int out_size) {
    const int*   edge_index = (const int*)  d_in[0];   // [2, E]
    const float* C          = (const float*)d_in[1];   // [E, 64]
    const float* W_L1       = (const float*)d_in[3];   // [64, 64]
    const float* W_L2       = (const float*)d_in[4];   // [64, 64]
    const float* W_mlp1     = (const float*)d_in[5];   // [512, 128]
    const float* W_mlp2     = (const float*)d_in[6];   // [64, 512]
    float* out = (float*)d_out;                        // [E, 64]

    int E = in_sizes[0] / 2;                           // 16384

    k_init<<<(NNODES * NNODES + 255) / 256, 256>>>();
    k_scatter<<<(E + 255) / 256, 256>>>(edge_index, E);
    k_xy<<<E / 8, 256>>>(C, W_L1, W_L2);
    k_paths<<<E, 64>>>(edge_index);

    cudaFuncSetAttribute(k_mlp, cudaFuncAttributeMaxDynamicSharedMemorySize, SMEM_TOT);
    k_mlp<<<E / 128, 256, SMEM_TOT>>>(W_mlp1, W_mlp2, out);
}

// round 4
// speedup vs baseline: 2.7996x; 1.1914x over previous
#include <cuda_runtime.h>
#include <cuda_bf16.h>
#include <cstdint>

#define NNODES 512
#define FDIM   64
#define EMAX   16384

// ---------------------------------------------------------------------------
// Scratch (static __device__ globals — no runtime allocation)
__device__ __align__(16) int      g_M  [NNODES * NNODES];   // edge id (valid only where bit set)
__device__ __align__(16) int      g_MT [NNODES * NNODES];
__device__ __align__(16) uint32_t g_Mb [NNODES * 16];       // 512-bit row masks
__device__ __align__(16) uint32_t g_MTb[NNODES * 16];
__device__ __align__(16) float    g_X  [EMAX * FDIM];
__device__ __align__(16) float    g_Y  [EMAX * FDIM];
__device__ __align__(16) float    g_tmp[EMAX * 2 * FDIM];   // [C | tmp_matmul]

// ---------------------------------------------------------------------------
__device__ __forceinline__ uint32_t smem_u32(const void* p) {
    uint32_t a;
    asm("{ .reg .u64 t; cvta.to.shared.u64 t, %1; cvt.u32.u64 %0, t; }" : "=r"(a) : "l"(p));
    return a;
}

// mma.sync m16n8k16 row.col bf16 -> f32 accumulate
__device__ __forceinline__ void mma16816(float* c, uint32_t a0, uint32_t a1,
                                         uint32_t a2, uint32_t a3,
                                         uint32_t b0, uint32_t b1) {
    asm("mma.sync.aligned.m16n8k16.row.col.f32.bf16.bf16.f32 "
        "{%0,%1,%2,%3}, {%4,%5,%6,%7}, {%8,%9}, {%0,%1,%2,%3};"
        : "+f"(c[0]), "+f"(c[1]), "+f"(c[2]), "+f"(c[3])
        : "r"(a0), "r"(a1), "r"(a2), "r"(a3), "r"(b0), "r"(b1));
}

__device__ __forceinline__ void ldmx4(uint32_t* r, uint32_t addr) {
    asm volatile("ldmatrix.sync.aligned.m8n8.x4.shared.b16 {%0,%1,%2,%3}, [%4];"
                 : "=r"(r[0]), "=r"(r[1]), "=r"(r[2]), "=r"(r[3]) : "r"(addr));
}

__device__ __forceinline__ uint32_t packbf(float x, float y) {
    __nv_bfloat162 t = __floats2bfloat162_rn(x, y);
    return *reinterpret_cast<uint32_t*>(&t);
}

// split a float4 into hi/lo bf16 pairs
__device__ __forceinline__ void split4(float4 v, uint2& hi, uint2& lo) {
    __nv_bfloat16 h0 = __float2bfloat16(v.x), h1 = __float2bfloat16(v.y);
    __nv_bfloat16 h2 = __float2bfloat16(v.z), h3 = __float2bfloat16(v.w);
    hi = make_uint2(packbf(__bfloat162float(h0), __bfloat162float(h1)),
                    packbf(__bfloat162float(h2), __bfloat162float(h3)));
    lo = make_uint2(packbf(v.x - __bfloat162float(h0), v.y - __bfloat162float(h1)),
                    packbf(v.z - __bfloat162float(h2), v.w - __bfloat162float(h3)));
}

// ---------------------------------------------------------------------------
__global__ void k_initmask() {
    int i = blockIdx.x * blockDim.x + threadIdx.x;
    if (i < NNODES * 16) { g_Mb[i] = 0u; g_MTb[i] = 0u; }
}

__global__ void k_scatter(const int* __restrict__ ei, int E) {
    int e = blockIdx.x * blockDim.x + threadIdx.x;
    if (e < E) {
        int i = ei[e];
        int k = ei[E + e];
        g_M [i * NNODES + k] = e;
        g_MT[k * NNODES + i] = e;
        atomicOr(&g_Mb [i * 16 + (k >> 5)], 1u << (k & 31));
        atomicOr(&g_MTb[k * 16 + (i >> 5)], 1u << (i & 31));
    }
}

// ---------------------------------------------------------------------------
// X = C@W1^T, Y = C@W2^T via mma.sync (bf16x3); also tmp[:, :64] = C.
// CTA = 128 edge rows, 256 threads (8 warps x 16 rows), K=N=64.
// SMEM row stride 128B; phys = r*128 + (kb ^ ((r&7)<<4)).
#define XY_CHI  0u
#define XY_CLO  16384u
#define XY_W1HI 32768u
#define XY_W1LO 40960u
#define XY_W2HI 49152u
#define XY_W2LO 57344u
#define XY_SMEM 65536u

__global__ __launch_bounds__(256, 1)
void k_xy(const float* __restrict__ C,
          const float* __restrict__ W1,
          const float* __restrict__ W2) {
    extern __shared__ char smem[];
    uint32_t sb = smem_u32(smem);
    int tid = threadIdx.x;
    int wid = tid >> 5, lane = tid & 31;
    int e0 = blockIdx.x * 128;
    int rw = wid * 16;

    // Stage C tile [128 x 64] -> hi/lo, and copy into g_tmp[:, :64]
    for (int i = tid; i < 2048; i += 256) {
        int r = i >> 4;
        int q = i & 15;                       // float4 index in row
        float4 v = *((const float4*)C + (size_t)(e0 + r) * 16 + q);
        ((float4*)g_tmp)[(size_t)(e0 + r) * 32 + q] = v;
        uint2 hi, lo;
        split4(v, hi, lo);
        uint32_t phys = (uint32_t)r * 128u + (((uint32_t)q * 8u) ^ (((uint32_t)r & 7u) << 4));
        *(uint2*)(smem + XY_CHI + phys) = hi;
        *(uint2*)(smem + XY_CLO + phys) = lo;
    }
    // Stage W1, W2 [64 x 64] -> hi/lo
    for (int i = tid; i < 2048; i += 256) {
        int w = i >> 10;                      // 0: W1, 1: W2
        int ii = i & 1023;
        int r = ii >> 4;
        int q = ii & 15;
        const float* W = w ? W2 : W1;
        float4 v = *((const float4*)W + r * 16 + q);
        uint2 hi, lo;
        split4(v, hi, lo);
        uint32_t phys = (uint32_t)r * 128u + (((uint32_t)q * 8u) ^ (((uint32_t)r & 7u) << 4));
        uint32_t hb = w ? XY_W2HI : XY_W1HI;
        uint32_t lb = w ? XY_W2LO : XY_W1LO;
        *(uint2*)(smem + hb + phys) = hi;
        *(uint2*)(smem + lb + phys) = lo;
    }
    __syncthreads();

    int l7 = lane & 7;
    int sel = lane >> 3;
    uint32_t xorv = (uint32_t)l7 << 4;
    uint32_t aRow = (uint32_t)(rw + (sel & 1) * 8 + l7) * 128u;
    uint32_t aKof = (uint32_t)(sel >> 1) * 16u;
    uint32_t bRow = (uint32_t)((sel >> 1) * 8 + l7) * 128u;
    uint32_t bKof = (uint32_t)(sel & 1) * 16u;

    float dX[8][4], dY[8][4];
    #pragma unroll
    for (int i = 0; i < 8; i++)
        #pragma unroll
        for (int j = 0; j < 4; j++) { dX[i][j] = 0.f; dY[i][j] = 0.f; }

    #pragma unroll
    for (int p = 0; p < 3; p++) {
        uint32_t abase = sb + (p == 2 ? XY_CLO : XY_CHI);
        uint32_t w1b   = sb + (p == 1 ? XY_W1LO : XY_W1HI);
        uint32_t w2b   = sb + (p == 1 ? XY_W2LO : XY_W2HI);
        #pragma unroll
        for (int ks = 0; ks < 4; ks++) {
            uint32_t kb = (uint32_t)ks * 32u;
            uint32_t a[4];
            ldmx4(a, abase + aRow + ((kb + aKof) ^ xorv));
            #pragma unroll
            for (int np = 0; np < 4; np++) {
                uint32_t off = (uint32_t)np * 2048u + bRow + ((kb + bKof) ^ xorv);
                uint32_t b[4];
                ldmx4(b, w1b + off);
                mma16816(dX[2 * np],     a[0], a[1], a[2], a[3], b[0], b[1]);
                mma16816(dX[2 * np + 1], a[0], a[1], a[2], a[3], b[2], b[3]);
                uint32_t b2[4];
                ldmx4(b2, w2b + off);
                mma16816(dY[2 * np],     a[0], a[1], a[2], a[3], b2[0], b2[1]);
                mma16816(dY[2 * np + 1], a[0], a[1], a[2], a[3], b2[2], b2[3]);
            }
        }
    }

    int r0 = e0 + rw + (lane >> 2);
    int c0 = (lane & 3) * 2;
    #pragma unroll
    for (int nt = 0; nt < 8; nt++) {
        *(float2*)(g_X + (size_t)r0 * 64 + nt * 8 + c0)       = make_float2(dX[nt][0], dX[nt][1]);
        *(float2*)(g_X + (size_t)(r0 + 8) * 64 + nt * 8 + c0) = make_float2(dX[nt][2], dX[nt][3]);
        *(float2*)(g_Y + (size_t)r0 * 64 + nt * 8 + c0)       = make_float2(dY[nt][0], dY[nt][1]);
        *(float2*)(g_Y + (size_t)(r0 + 8) * 64 + nt * 8 + c0) = make_float2(dY[nt][2], dY[nt][3]);
    }
}

// ---------------------------------------------------------------------------
// Sparse path contraction via bitmask intersection. 1 warp per edge.
__global__ __launch_bounds__(128)
void k_paths(const int* __restrict__ ei, int E) {
    __shared__ int2 pairs[4][512];
    __shared__ int  cnt[4];
    int w = threadIdx.x >> 5, lane = threadIdx.x & 31;
    int e = blockIdx.x * 4 + w;
    int i = ei[e];
    int k = ei[E + e];
    if (lane == 0) cnt[w] = 0;
    __syncwarp();
    uint32_t m = (lane < 16) ? (g_Mb[i * 16 + lane] & g_MTb[k * 16 + lane]) : 0u;
    while (m) {
        int b = __ffs(m) - 1;
        m &= m - 1;
        int j = (lane << 5) + b;
        int p = atomicAdd(&cnt[w], 1);
        pairs[w][p] = make_int2(g_M[i * NNODES + j], g_MT[k * NNODES + j]);
    }
    __syncwarp();
    int n = cnt[w];
    float2 acc = make_float2(0.f, 0.f);
    const float2* Xb = (const float2*)g_X;
    const float2* Yb = (const float2*)g_Y;
    for (int p = 0; p < n; p++) {
        int2 pr = pairs[w][p];
        float2 x = Xb[(size_t)pr.x * 32 + lane];
        float2 y = Yb[(size_t)pr.y * 32 + lane];
        acc.x = fmaf(x.x, y.x, acc.x);
        acc.y = fmaf(x.y, y.y, acc.y);
    }
    ((float2*)g_tmp)[(size_t)e * 64 + 32 + lane] = acc;
}

// ---------------------------------------------------------------------------
// Fused MLP via mma.sync (bf16x3). CTA = 128 edges, 256 threads.
#define OFF_AHI 0u
#define OFF_ALO 32768u
#define OFF_BHI 65536u
#define OFF_BLO 98304u
#define SMEM_TOT 131072u

__device__ __forceinline__ void stage_tile(char* smem, uint32_t hiOff, uint32_t loOff,
                                           const float4* src, int nfloat4, int tid) {
    for (int i = tid; i < nfloat4; i += 256) {
        float4 v = src[i];
        int r = i >> 5;
        int kb = (i & 31) * 8;
        uint2 hi, lo;
        split4(v, hi, lo);
        uint32_t phys = (uint32_t)r * 256u + ((uint32_t)kb ^ (((uint32_t)r & 7u) << 4));
        *(uint2*)(smem + hiOff + phys) = hi;
        *(uint2*)(smem + loOff + phys) = lo;
    }
}

__global__ __launch_bounds__(256, 1)
void k_mlp(const float* __restrict__ W1,   // [512,128]
           const float* __restrict__ W2,   // [64,512]
           float* __restrict__ out) {      // [E,64]
    extern __shared__ char smem[];
    uint32_t sb = smem_u32(smem);
    int tid = threadIdx.x;
    int wid = tid >> 5, lane = tid & 31;
    int e0 = blockIdx.x * 128;
    int rw = wid * 16;

    int l7 = lane & 7;
    int sel = lane >> 3;
    uint32_t xorv = (uint32_t)l7 << 4;
    uint32_t aRow = (uint32_t)(rw + (sel & 1) * 8 + l7) * 256u;
    uint32_t aKof = (uint32_t)(sel >> 1) * 16u;
    uint32_t bRowBase = (uint32_t)((sel >> 1) * 8 + l7) * 256u;
    uint32_t bKof = (uint32_t)(sel & 1) * 16u;

    float d2a[8][4];
    #pragma unroll
    for (int i = 0; i < 8; i++)
        #pragma unroll
        for (int j = 0; j < 4; j++) d2a[i][j] = 0.f;

    // Stage A = tmp[e0:e0+128, 0:128]
    stage_tile(smem, OFF_AHI, OFF_ALO, (const float4*)g_tmp + (size_t)e0 * 32, 4096, tid);

    for (int c = 0; c < 4; c++) {
        __syncthreads();
        // Stage B1 = W1 rows [c*128, c*128+128)
        stage_tile(smem, OFF_BHI, OFF_BLO, (const float4*)W1 + c * 4096, 4096, tid);
        __syncthreads();

        float d1[16][4];
        #pragma unroll
        for (int i = 0; i < 16; i++)
            #pragma unroll
            for (int j = 0; j < 4; j++) d1[i][j] = 0.f;

        // MMA1: d1 += A @ B1^T (3 bf16 passes)
        #pragma unroll
        for (int p = 0; p < 3; p++) {
            uint32_t abase = sb + (p == 2 ? OFF_ALO : OFF_AHI);
            uint32_t bbase = sb + (p == 1 ? OFF_BLO : OFF_BHI);
            #pragma unroll
            for (int ks = 0; ks < 8; ks++) {
                uint32_t kb = (uint32_t)ks * 32u;
                uint32_t a[4];
                ldmx4(a, abase + aRow + ((kb + aKof) ^ xorv));
                #pragma unroll
                for (int np = 0; np < 8; np++) {
                    uint32_t b[4];
                    ldmx4(b, bbase + (uint32_t)np * 4096u + bRowBase + ((kb + bKof) ^ xorv));
                    mma16816(d1[2 * np],     a[0], a[1], a[2], a[3], b[0], b[1]);
                    mma16816(d1[2 * np + 1], a[0], a[1], a[2], a[3], b[2], b[3]);
                }
            }
        }

        __syncthreads();
        // Stage B2 = W2[0:64, c*128 : c*128+128)
        for (int i = tid; i < 2048; i += 256) {
            int r = i >> 5;
            int k4 = (i & 31) * 4;
            float4 v = *(const float4*)(W2 + r * 512 + c * 128 + k4);
            int kb = (i & 31) * 8;
            uint2 hi, lo;
            split4(v, hi, lo);
            uint32_t phys = (uint32_t)r * 256u + ((uint32_t)kb ^ (((uint32_t)r & 7u) << 4));
            *(uint2*)(smem + OFF_BHI + phys) = hi;
            *(uint2*)(smem + OFF_BLO + phys) = lo;
        }
        __syncthreads();

        // MMA2: d2a += relu(d1) @ B2^T (H stays in registers)
        #pragma unroll
        for (int kt = 0; kt < 8; kt++) {
            float va0 = fmaxf(d1[2 * kt][0], 0.f), va1 = fmaxf(d1[2 * kt][1], 0.f);
            float va2 = fmaxf(d1[2 * kt][2], 0.f), va3 = fmaxf(d1[2 * kt][3], 0.f);
            float vb0 = fmaxf(d1[2 * kt + 1][0], 0.f), vb1 = fmaxf(d1[2 * kt + 1][1], 0.f);
            float vb2 = fmaxf(d1[2 * kt + 1][2], 0.f), vb3 = fmaxf(d1[2 * kt + 1][3], 0.f);
            float ha0 = __bfloat162float(__float2bfloat16(va0));
            float ha1 = __bfloat162float(__float2bfloat16(va1));
            float ha2 = __bfloat162float(__float2bfloat16(va2));
            float ha3 = __bfloat162float(__float2bfloat16(va3));
            float hb0 = __bfloat162float(__float2bfloat16(vb0));
            float hb1 = __bfloat162float(__float2bfloat16(vb1));
            float hb2 = __bfloat162float(__float2bfloat16(vb2));
            float hb3 = __bfloat162float(__float2bfloat16(vb3));
            uint32_t ah[4] = { packbf(ha0, ha1), packbf(ha2, ha3),
                               packbf(hb0, hb1), packbf(hb2, hb3) };
            uint32_t al[4] = { packbf(va0 - ha0, va1 - ha1), packbf(va2 - ha2, va3 - ha3),
                               packbf(vb0 - hb0, vb1 - hb1), packbf(vb2 - hb2, vb3 - hb3) };
            uint32_t kb = (uint32_t)kt * 32u;
            #pragma unroll
            for (int np = 0; np < 4; np++) {
                uint32_t bh[4], bl[4];
                uint32_t off = (uint32_t)np * 4096u + bRowBase + ((kb + bKof) ^ xorv);
                ldmx4(bh, sb + OFF_BHI + off);
                ldmx4(bl, sb + OFF_BLO + off);
                mma16816(d2a[2 * np],     ah[0], ah[1], ah[2], ah[3], bh[0], bh[1]);
                mma16816(d2a[2 * np + 1], ah[0], ah[1], ah[2], ah[3], bh[2], bh[3]);
                mma16816(d2a[2 * np],     ah[0], ah[1], ah[2], ah[3], bl[0], bl[1]);
                mma16816(d2a[2 * np + 1], ah[0], ah[1], ah[2], ah[3], bl[2], bl[3]);
                mma16816(d2a[2 * np],     al[0], al[1], al[2], al[3], bh[0], bh[1]);
                mma16816(d2a[2 * np + 1], al[0], al[1], al[2], al[3], bh[2], bh[3]);
            }
        }
    }

    int r0 = e0 + rw + (lane >> 2);
    int c0 = (lane & 3) * 2;
    #pragma unroll
    for (int nt = 0; nt < 8; nt++) {
        *(float2*)(out + (size_t)r0 * 64 + nt * 8 + c0)       = make_float2(d2a[nt][0], d2a[nt][1]);
        *(float2*)(out + (size_t)(r0 + 8) * 64 + nt * 8 + c0) = make_float2(d2a[nt][2], d2a[nt][3]);
    }
}

// ---------------------------------------------------------------------------
extern "C" void kernel_launch(void* const* d_in, const int* in_sizes, int n_in,
                              void* d_out, int out_size) {
    const int*   edge_index = (const int*)  d_in[0];   // [2, E]
    const float* C          = (const float*)d_in[1];   // [E, 64]
    const float* W_L1       = (const float*)d_in[3];   // [64, 64]
    const float* W_L2       = (const float*)d_in[4];   // [64, 64]
    const float* W_mlp1     = (const float*)d_in[5];   // [512, 128]
    const float* W_mlp2     = (const float*)d_in[6];   // [64, 512]
    float* out = (float*)d_out;                        // [E, 64]

    int E = in_sizes[0] / 2;                           // 16384

    k_initmask<<<(NNODES * 16 + 255) / 256, 256>>>();
    k_scatter<<<(E + 255) / 256, 256>>>(edge_index, E);

    cudaFuncSetAttribute(k_xy, cudaFuncAttributeMaxDynamicSharedMemorySize, XY_SMEM);
    k_xy<<<E / 128, 256, XY_SMEM>>>(C, W_L1, W_L2);

    k_paths<<<E / 4, 128>>>(edge_index, E);

    cudaFuncSetAttribute(k_mlp, cudaFuncAttributeMaxDynamicSharedMemorySize, SMEM_TOT);
    k_mlp<<<E / 128, 256, SMEM_TOT>>>(W_mlp1, W_mlp2, out);
}

// round 5
// speedup vs baseline: 3.0665x; 1.0953x over previous
#include <cuda_runtime.h>
#include <cuda_bf16.h>
#include <cstdint>

#define NNODES 512
#define FDIM   64
#define EMAX   16384
#define PMAX   24

// ---------------------------------------------------------------------------
// Scratch (static __device__ globals — no runtime allocation)
__device__ __align__(16) unsigned short g_M16 [NNODES * NNODES];  // edge id (valid where bit set)
__device__ __align__(16) unsigned short g_MT16[NNODES * NNODES];
__device__ __align__(16) uint32_t g_Mb [NNODES * 16];             // 512-bit row masks
__device__ __align__(16) uint32_t g_MTb[NNODES * 16];
__device__ __align__(16) float    g_X  [EMAX * FDIM];
__device__ __align__(16) float    g_Y  [EMAX * FDIM];

// ---------------------------------------------------------------------------
__device__ __forceinline__ uint32_t smem_u32(const void* p) {
    uint32_t a;
    asm("{ .reg .u64 t; cvta.to.shared.u64 t, %1; cvt.u32.u64 %0, t; }" : "=r"(a) : "l"(p));
    return a;
}

__device__ __forceinline__ void mma16816(float* c, const uint32_t* a,
                                         uint32_t b0, uint32_t b1) {
    asm("mma.sync.aligned.m16n8k16.row.col.f32.bf16.bf16.f32 "
        "{%0,%1,%2,%3}, {%4,%5,%6,%7}, {%8,%9}, {%0,%1,%2,%3};"
        : "+f"(c[0]), "+f"(c[1]), "+f"(c[2]), "+f"(c[3])
        : "r"(a[0]), "r"(a[1]), "r"(a[2]), "r"(a[3]), "r"(b0), "r"(b1));
}

__device__ __forceinline__ void ldmx4(uint32_t* r, uint32_t addr) {
    asm volatile("ldmatrix.sync.aligned.m8n8.x4.shared.b16 {%0,%1,%2,%3}, [%4];"
                 : "=r"(r[0]), "=r"(r[1]), "=r"(r[2]), "=r"(r[3]) : "r"(addr));
}

__device__ __forceinline__ uint32_t packbf(float x, float y) {
    __nv_bfloat162 t = __floats2bfloat162_rn(x, y);
    return *reinterpret_cast<uint32_t*>(&t);
}

__device__ __forceinline__ void split4(float4 v, uint2& hi, uint2& lo) {
    __nv_bfloat16 h0 = __float2bfloat16(v.x), h1 = __float2bfloat16(v.y);
    __nv_bfloat16 h2 = __float2bfloat16(v.z), h3 = __float2bfloat16(v.w);
    hi = make_uint2(packbf(__bfloat162float(h0), __bfloat162float(h1)),
                    packbf(__bfloat162float(h2), __bfloat162float(h3)));
    lo = make_uint2(packbf(v.x - __bfloat162float(h0), v.y - __bfloat162float(h1)),
                    packbf(v.z - __bfloat162float(h2), v.w - __bfloat162float(h3)));
}

// ---------------------------------------------------------------------------
__global__ void k_initmask() {
    int i = blockIdx.x * blockDim.x + threadIdx.x;
    if (i < NNODES * 16) { g_Mb[i] = 0u; g_MTb[i] = 0u; }
}

// ---------------------------------------------------------------------------
// Fused: edge scatter + (X = C@W1^T, Y = C@W2^T) via mma.sync bf16x3.
// CTA = 128 edge rows, 256 threads (8 warps x 16 rows), K=N=64.
#define XY_CHI  0u
#define XY_CLO  16384u
#define XY_W1HI 32768u
#define XY_W1LO 40960u
#define XY_W2HI 49152u
#define XY_W2LO 57344u
#define XY_SMEM 65536u

__global__ __launch_bounds__(256, 1)
void k_xy(const int* __restrict__ ei,
          const float* __restrict__ C,
          const float* __restrict__ W1,
          const float* __restrict__ W2, int E) {
    extern __shared__ char smem[];
    uint32_t sb = smem_u32(smem);
    int tid = threadIdx.x;
    int wid = tid >> 5, lane = tid & 31;
    int e0 = blockIdx.x * 128;
    int rw = wid * 16;

    // --- scatter (half the grid's threads; independent of GEMM below)
    {
        int g = blockIdx.x * 128 + tid;   // E/128 blocks * 256 threads covers E with tid<128... use full id
        g = blockIdx.x * 256 + tid;
        if (g < E) {
            int i = ei[g];
            int k = ei[E + g];
            g_M16 [i * NNODES + k] = (unsigned short)g;
            g_MT16[k * NNODES + i] = (unsigned short)g;
            atomicOr(&g_Mb [i * 16 + (k >> 5)], 1u << (k & 31));
            atomicOr(&g_MTb[k * 16 + (i >> 5)], 1u << (i & 31));
        }
    }

    // --- stage C tile [128 x 64] -> hi/lo
    for (int i = tid; i < 2048; i += 256) {
        int r = i >> 4;
        int q = i & 15;
        float4 v = *((const float4*)C + (size_t)(e0 + r) * 16 + q);
        uint2 hi, lo;
        split4(v, hi, lo);
        uint32_t phys = (uint32_t)r * 128u + (((uint32_t)q * 8u) ^ (((uint32_t)r & 7u) << 4));
        *(uint2*)(smem + XY_CHI + phys) = hi;
        *(uint2*)(smem + XY_CLO + phys) = lo;
    }
    // --- stage W1, W2 [64 x 64] -> hi/lo
    for (int i = tid; i < 2048; i += 256) {
        int w = i >> 10;
        int ii = i & 1023;
        int r = ii >> 4;
        int q = ii & 15;
        const float* W = w ? W2 : W1;
        float4 v = *((const float4*)W + r * 16 + q);
        uint2 hi, lo;
        split4(v, hi, lo);
        uint32_t phys = (uint32_t)r * 128u + (((uint32_t)q * 8u) ^ (((uint32_t)r & 7u) << 4));
        *(uint2*)(smem + (w ? XY_W2HI : XY_W1HI) + phys) = hi;
        *(uint2*)(smem + (w ? XY_W2LO : XY_W1LO) + phys) = lo;
    }
    __syncthreads();

    int l7 = lane & 7;
    int sel = lane >> 3;
    uint32_t xorv = (uint32_t)l7 << 4;
    uint32_t aRow = (uint32_t)(rw + (sel & 1) * 8 + l7) * 128u;
    uint32_t aKof = (uint32_t)(sel >> 1) * 16u;
    uint32_t bRow = (uint32_t)((sel >> 1) * 8 + l7) * 128u;
    uint32_t bKof = (uint32_t)(sel & 1) * 16u;

    float dX[8][4], dY[8][4];
    #pragma unroll
    for (int i = 0; i < 8; i++)
        #pragma unroll
        for (int j = 0; j < 4; j++) { dX[i][j] = 0.f; dY[i][j] = 0.f; }

    #pragma unroll
    for (int ks = 0; ks < 4; ks++) {
        uint32_t kb = (uint32_t)ks * 32u;
        uint32_t ch[4], cl[4];
        ldmx4(ch, sb + XY_CHI + aRow + ((kb + aKof) ^ xorv));
        ldmx4(cl, sb + XY_CLO + aRow + ((kb + aKof) ^ xorv));
        #pragma unroll
        for (int np = 0; np < 4; np++) {
            uint32_t off = (uint32_t)np * 2048u + bRow + ((kb + bKof) ^ xorv);
            uint32_t b1h[4], b1l[4], b2h[4], b2l[4];
            ldmx4(b1h, sb + XY_W1HI + off);
            ldmx4(b1l, sb + XY_W1LO + off);
            ldmx4(b2h, sb + XY_W2HI + off);
            ldmx4(b2l, sb + XY_W2LO + off);
            mma16816(dX[2 * np],     ch, b1h[0], b1h[1]);
            mma16816(dX[2 * np + 1], ch, b1h[2], b1h[3]);
            mma16816(dX[2 * np],     ch, b1l[0], b1l[1]);
            mma16816(dX[2 * np + 1], ch, b1l[2], b1l[3]);
            mma16816(dX[2 * np],     cl, b1h[0], b1h[1]);
            mma16816(dX[2 * np + 1], cl, b1h[2], b1h[3]);
            mma16816(dY[2 * np],     ch, b2h[0], b2h[1]);
            mma16816(dY[2 * np + 1], ch, b2h[2], b2h[3]);
            mma16816(dY[2 * np],     ch, b2l[0], b2l[1]);
            mma16816(dY[2 * np + 1], ch, b2l[2], b2l[3]);
            mma16816(dY[2 * np],     cl, b2h[0], b2h[1]);
            mma16816(dY[2 * np + 1], cl, b2h[2], b2h[3]);
        }
    }

    int r0 = e0 + rw + (lane >> 2);
    int c0 = (lane & 3) * 2;
    #pragma unroll
    for (int nt = 0; nt < 8; nt++) {
        *(float2*)(g_X + (size_t)r0 * 64 + nt * 8 + c0)       = make_float2(dX[nt][0], dX[nt][1]);
        *(float2*)(g_X + (size_t)(r0 + 8) * 64 + nt * 8 + c0) = make_float2(dX[nt][2], dX[nt][3]);
        *(float2*)(g_Y + (size_t)r0 * 64 + nt * 8 + c0)       = make_float2(dY[nt][0], dY[nt][1]);
        *(float2*)(g_Y + (size_t)(r0 + 8) * 64 + nt * 8 + c0) = make_float2(dY[nt][2], dY[nt][3]);
    }
}

// ---------------------------------------------------------------------------
// Fused path-contraction + MLP. CTA = 128 edges, 256 threads.
#define OFF_AHI   0u
#define OFF_ALO   32768u
#define OFF_BHI   65536u
#define OFF_BLO   98304u
#define OFF_PAIRS 131072u                         // 128 * PMAX * 4B = 12KB
#define OFF_CNT   (OFF_PAIRS + 128u * PMAX * 4u)
#define OFF_EI    (OFF_CNT + 512u)
#define SMEM_TOT  (OFF_EI + 1024u)

__global__ __launch_bounds__(256, 1)
void k_mlp(const int* __restrict__ ei,
           const float* __restrict__ C,    // [E,64]
           const float* __restrict__ W1,   // [512,128]
           const float* __restrict__ W2,   // [64,512]
           float* __restrict__ out, int E) {
    extern __shared__ char smem[];
    uint32_t sb = smem_u32(smem);
    uint32_t* s_pairs = (uint32_t*)(smem + OFF_PAIRS);
    int*      s_cnt   = (int*)(smem + OFF_CNT);
    int*      s_ei    = (int*)(smem + OFF_EI);
    int tid = threadIdx.x;
    int wid = tid >> 5, lane = tid & 31;
    int e0 = blockIdx.x * 128;
    int rw = wid * 16;

    // ---- prologue: load edge endpoints, zero pair counts
    if (tid < 128) s_ei[tid] = ei[e0 + tid];
    else           s_ei[tid] = ei[E + e0 + tid - 128];
    if (lane < 16) s_cnt[rw + lane] = 0;

    // ---- stage A cols 0-63 from C (independent, loads in flight early)
    for (int i = tid; i < 2048; i += 256) {
        int r = i >> 4;
        int q = i & 15;
        float4 v = *((const float4*)C + (size_t)(e0 + r) * 16 + q);
        uint2 hi, lo;
        split4(v, hi, lo);
        uint32_t phys = (uint32_t)r * 256u + (((uint32_t)q * 8u) ^ (((uint32_t)r & 7u) << 4));
        *(uint2*)(smem + OFF_AHI + phys) = hi;
        *(uint2*)(smem + OFF_ALO + phys) = lo;
    }
    __syncthreads();

    // ---- phase 1: pair extraction (2 threads per edge, 8 mask words each)
    {
        int le = tid >> 1;
        int i = s_ei[le], k = s_ei[128 + le];
        int wb = (tid & 1) * 8;
        const uint32_t* mb  = &g_Mb [i * 16 + wb];
        const uint32_t* mtb = &g_MTb[k * 16 + wb];
        #pragma unroll
        for (int w8 = 0; w8 < 8; w8++) {
            uint32_t m = mb[w8] & mtb[w8];
            while (m) {
                int b = __ffs(m) - 1;
                m &= m - 1;
                int j = (wb + w8) * 32 + b;
                uint32_t e1 = g_M16 [i * NNODES + j];
                uint32_t e2 = g_MT16[k * NNODES + j];
                int p = atomicAdd(&s_cnt[le], 1);
                if (p < PMAX) s_pairs[le * PMAX + p] = e1 | (e2 << 16);
            }
        }
    }
    __syncwarp();

    // ---- phase 2: accumulate per-edge path products -> A cols 64-127
    {
        const float2* Xb = (const float2*)g_X;
        const float2* Yb = (const float2*)g_Y;
        for (int t = 0; t < 16; t++) {
            int le = rw + t;
            int n = s_cnt[le];
            n = n < PMAX ? n : PMAX;
            float2 acc = make_float2(0.f, 0.f);
            int p = 0;
            for (; p + 2 <= n; p += 2) {
                uint32_t pr0 = s_pairs[le * PMAX + p];
                uint32_t pr1 = s_pairs[le * PMAX + p + 1];
                float2 x0 = Xb[(size_t)(pr0 & 0xffffu) * 32 + lane];
                float2 y0 = Yb[(size_t)(pr0 >> 16) * 32 + lane];
                float2 x1 = Xb[(size_t)(pr1 & 0xffffu) * 32 + lane];
                float2 y1 = Yb[(size_t)(pr1 >> 16) * 32 + lane];
                acc.x = fmaf(x0.x, y0.x, acc.x);
                acc.y = fmaf(x0.y, y0.y, acc.y);
                acc.x = fmaf(x1.x, y1.x, acc.x);
                acc.y = fmaf(x1.y, y1.y, acc.y);
            }
            if (p < n) {
                uint32_t pr = s_pairs[le * PMAX + p];
                float2 x = Xb[(size_t)(pr & 0xffffu) * 32 + lane];
                float2 y = Yb[(size_t)(pr >> 16) * 32 + lane];
                acc.x = fmaf(x.x, y.x, acc.x);
                acc.y = fmaf(x.y, y.y, acc.y);
            }
            __nv_bfloat16 h0 = __float2bfloat16(acc.x), h1 = __float2bfloat16(acc.y);
            uint32_t hi = packbf(__bfloat162float(h0), __bfloat162float(h1));
            uint32_t lo = packbf(acc.x - __bfloat162float(h0), acc.y - __bfloat162float(h1));
            uint32_t kb = 128u + (uint32_t)lane * 4u;
            uint32_t phys = (uint32_t)le * 256u + (kb ^ (((uint32_t)le & 7u) << 4));
            *(uint32_t*)(smem + OFF_AHI + phys) = hi;
            *(uint32_t*)(smem + OFF_ALO + phys) = lo;
        }
    }

    // ---- MLP main loop
    int l7 = lane & 7;
    int sel = lane >> 3;
    uint32_t xorv = (uint32_t)l7 << 4;
    uint32_t aRow = (uint32_t)(rw + (sel & 1) * 8 + l7) * 256u;
    uint32_t aKof = (uint32_t)(sel >> 1) * 16u;
    uint32_t bRowBase = (uint32_t)((sel >> 1) * 8 + l7) * 256u;
    uint32_t bKof = (uint32_t)(sel & 1) * 16u;

    float d2a[8][4];
    #pragma unroll
    for (int i = 0; i < 8; i++)
        #pragma unroll
        for (int j = 0; j < 4; j++) d2a[i][j] = 0.f;

    for (int c = 0; c < 4; c++) {
        __syncthreads();
        // stage B1 = W1 rows [c*128, c*128+128)
        for (int i = tid; i < 4096; i += 256) {
            float4 v = ((const float4*)W1)[c * 4096 + i];
            int r = i >> 5;
            int kb = (i & 31) * 8;
            uint2 hi, lo;
            split4(v, hi, lo);
            uint32_t phys = (uint32_t)r * 256u + ((uint32_t)kb ^ (((uint32_t)r & 7u) << 4));
            *(uint2*)(smem + OFF_BHI + phys) = hi;
            *(uint2*)(smem + OFF_BLO + phys) = lo;
        }
        __syncthreads();

        float d1[16][4];
        #pragma unroll
        for (int i = 0; i < 16; i++)
            #pragma unroll
            for (int j = 0; j < 4; j++) d1[i][j] = 0.f;

        // MMA1: d1 += A @ B1^T (bf16x3; shared A/B loads across the 3 passes)
        #pragma unroll
        for (int ks = 0; ks < 8; ks++) {
            uint32_t kb = (uint32_t)ks * 32u;
            uint32_t ah[4], al[4];
            ldmx4(ah, sb + OFF_AHI + aRow + ((kb + aKof) ^ xorv));
            ldmx4(al, sb + OFF_ALO + aRow + ((kb + aKof) ^ xorv));
            #pragma unroll
            for (int np = 0; np < 8; np++) {
                uint32_t off = (uint32_t)np * 4096u + bRowBase + ((kb + bKof) ^ xorv);
                uint32_t bh[4], bl[4];
                ldmx4(bh, sb + OFF_BHI + off);
                ldmx4(bl, sb + OFF_BLO + off);
                mma16816(d1[2 * np],     ah, bh[0], bh[1]);
                mma16816(d1[2 * np + 1], ah, bh[2], bh[3]);
                mma16816(d1[2 * np],     ah, bl[0], bl[1]);
                mma16816(d1[2 * np + 1], ah, bl[2], bl[3]);
                mma16816(d1[2 * np],     al, bh[0], bh[1]);
                mma16816(d1[2 * np + 1], al, bh[2], bh[3]);
            }
        }

        __syncthreads();
        // stage B2 = W2[0:64, c*128 : c*128+128)
        for (int i = tid; i < 2048; i += 256) {
            int r = i >> 5;
            int k4 = (i & 31) * 4;
            float4 v = *(const float4*)(W2 + r * 512 + c * 128 + k4);
            int kb = (i & 31) * 8;
            uint2 hi, lo;
            split4(v, hi, lo);
            uint32_t phys = (uint32_t)r * 256u + ((uint32_t)kb ^ (((uint32_t)r & 7u) << 4));
            *(uint2*)(smem + OFF_BHI + phys) = hi;
            *(uint2*)(smem + OFF_BLO + phys) = lo;
        }
        __syncthreads();

        // MMA2: d2a += relu(d1) @ B2^T (H stays in registers)
        #pragma unroll
        for (int kt = 0; kt < 8; kt++) {
            float va0 = fmaxf(d1[2 * kt][0], 0.f), va1 = fmaxf(d1[2 * kt][1], 0.f);
            float va2 = fmaxf(d1[2 * kt][2], 0.f), va3 = fmaxf(d1[2 * kt][3], 0.f);
            float vb0 = fmaxf(d1[2 * kt + 1][0], 0.f), vb1 = fmaxf(d1[2 * kt + 1][1], 0.f);
            float vb2 = fmaxf(d1[2 * kt + 1][2], 0.f), vb3 = fmaxf(d1[2 * kt + 1][3], 0.f);
            float ha0 = __bfloat162float(__float2bfloat16(va0));
            float ha1 = __bfloat162float(__float2bfloat16(va1));
            float ha2 = __bfloat162float(__float2bfloat16(va2));
            float ha3 = __bfloat162float(__float2bfloat16(va3));
            float hb0 = __bfloat162float(__float2bfloat16(vb0));
            float hb1 = __bfloat162float(__float2bfloat16(vb1));
            float hb2 = __bfloat162float(__float2bfloat16(vb2));
            float hb3 = __bfloat162float(__float2bfloat16(vb3));
            uint32_t ah[4] = { packbf(ha0, ha1), packbf(ha2, ha3),
                               packbf(hb0, hb1), packbf(hb2, hb3) };
            uint32_t al[4] = { packbf(va0 - ha0, va1 - ha1), packbf(va2 - ha2, va3 - ha3),
                               packbf(vb0 - hb0, vb1 - hb1), packbf(vb2 - hb2, vb3 - hb3) };
            uint32_t kb = (uint32_t)kt * 32u;
            #pragma unroll
            for (int np = 0; np < 4; np++) {
                uint32_t bh[4], bl[4];
                uint32_t off = (uint32_t)np * 4096u + bRowBase + ((kb + bKof) ^ xorv);
                ldmx4(bh, sb + OFF_BHI + off);
                ldmx4(bl, sb + OFF_BLO + off);
                mma16816(d2a[2 * np],     ah, bh[0], bh[1]);
                mma16816(d2a[2 * np + 1], ah, bh[2], bh[3]);
                mma16816(d2a[2 * np],     ah, bl[0], bl[1]);
                mma16816(d2a[2 * np + 1], ah, bl[2], bl[3]);
                mma16816(d2a[2 * np],     al, bh[0], bh[1]);
                mma16816(d2a[2 * np + 1], al, bh[2], bh[3]);
            }
        }
    }

    int r0 = e0 + rw + (lane >> 2);
    int c0 = (lane & 3) * 2;
    #pragma unroll
    for (int nt = 0; nt < 8; nt++) {
        *(float2*)(out + (size_t)r0 * 64 + nt * 8 + c0)       = make_float2(d2a[nt][0], d2a[nt][1]);
        *(float2*)(out + (size_t)(r0 + 8) * 64 + nt * 8 + c0) = make_float2(d2a[nt][2], d2a[nt][3]);
    }
}

// ---------------------------------------------------------------------------
extern "C" void kernel_launch(void* const* d_in, const int* in_sizes, int n_in,
                              void* d_out, int out_size) {
    const int*   edge_index = (const int*)  d_in[0];   // [2, E]
    const float* C          = (const float*)d_in[1];   // [E, 64]
    const float* W_L1       = (const float*)d_in[3];   // [64, 64]
    const float* W_L2       = (const float*)d_in[4];   // [64, 64]
    const float* W_mlp1     = (const float*)d_in[5];   // [512, 128]
    const float* W_mlp2     = (const float*)d_in[6];   // [64, 512]
    float* out = (float*)d_out;                        // [E, 64]

    int E = in_sizes[0] / 2;                           // 16384

    k_initmask<<<(NNODES * 16 + 255) / 256, 256>>>();

    cudaFuncSetAttribute(k_xy, cudaFuncAttributeMaxDynamicSharedMemorySize, XY_SMEM);
    k_xy<<<E / 128, 256, XY_SMEM>>>(edge_index, C, W_L1, W_L2, E);

    cudaFuncSetAttribute(k_mlp, cudaFuncAttributeMaxDynamicSharedMemorySize, SMEM_TOT);
    k_mlp<<<E / 128, 256, SMEM_TOT>>>(edge_index, C, W_mlp1, W_mlp2, out, E);
}

// round 6
// speedup vs baseline: 3.8375x; 1.2515x over previous
#include <cuda_runtime.h>
#include <cuda_bf16.h>
#include <cstdint>

#define NNODES 512
#define EMAX   16384
#define PMAX   24

// ---------------------------------------------------------------------------
// Scratch (static __device__ globals — no runtime allocation)
__device__ __align__(16) unsigned short g_M16 [NNODES * NNODES];
__device__ __align__(16) unsigned short g_MT16[NNODES * NNODES];
__device__ __align__(16) uint32_t g_Mb [NNODES * 16];
__device__ __align__(16) uint32_t g_MTb[NNODES * 16];
__device__ __align__(16) float    g_X  [EMAX * 64];
__device__ __align__(16) float    g_Y  [EMAX * 64];
// pre-split bf16 operands (pre-swizzled tile layouts)
__device__ __align__(16) char g_Cs_hi [EMAX * 128];      // C rows, 128B/row
__device__ __align__(16) char g_Cs_lo [EMAX * 128];
__device__ __align__(16) char g_W1s_hi[4 * 32768];       // W1 chunks, 256B/row
__device__ __align__(16) char g_W1s_lo[4 * 32768];
__device__ __align__(16) char g_W2s_hi[4 * 16384];       // W2 chunks, 256B/row
__device__ __align__(16) char g_W2s_lo[4 * 16384];
__device__ __align__(16) char g_Wxy   [4 * 8192];        // W_L1 hi, W_L1 lo, W_L2 hi, W_L2 lo

// ---------------------------------------------------------------------------
__device__ __forceinline__ uint32_t smem_u32(const void* p) {
    uint32_t a;
    asm("{ .reg .u64 t; cvta.to.shared.u64 t, %1; cvt.u32.u64 %0, t; }" : "=r"(a) : "l"(p));
    return a;
}
__device__ __forceinline__ void mma16816(float* c, const uint32_t* a,
                                         uint32_t b0, uint32_t b1) {
    asm("mma.sync.aligned.m16n8k16.row.col.f32.bf16.bf16.f32 "
        "{%0,%1,%2,%3}, {%4,%5,%6,%7}, {%8,%9}, {%0,%1,%2,%3};"
        : "+f"(c[0]), "+f"(c[1]), "+f"(c[2]), "+f"(c[3])
        : "r"(a[0]), "r"(a[1]), "r"(a[2]), "r"(a[3]), "r"(b0), "r"(b1));
}
__device__ __forceinline__ void ldmx4(uint32_t* r, uint32_t addr) {
    asm volatile("ldmatrix.sync.aligned.m8n8.x4.shared.b16 {%0,%1,%2,%3}, [%4];"
                 : "=r"(r[0]), "=r"(r[1]), "=r"(r[2]), "=r"(r[3]) : "r"(addr));
}
__device__ __forceinline__ uint32_t packbf(float x, float y) {
    __nv_bfloat162 t = __floats2bfloat162_rn(x, y);
    return *reinterpret_cast<uint32_t*>(&t);
}
__device__ __forceinline__ void split4(float4 v, uint2& hi, uint2& lo) {
    __nv_bfloat16 h0 = __float2bfloat16(v.x), h1 = __float2bfloat16(v.y);
    __nv_bfloat16 h2 = __float2bfloat16(v.z), h3 = __float2bfloat16(v.w);
    hi = make_uint2(packbf(__bfloat162float(h0), __bfloat162float(h1)),
                    packbf(__bfloat162float(h2), __bfloat162float(h3)));
    lo = make_uint2(packbf(v.x - __bfloat162float(h0), v.y - __bfloat162float(h1)),
                    packbf(v.z - __bfloat162float(h2), v.w - __bfloat162float(h3)));
}
__device__ __forceinline__ void cpasync16(uint32_t dst, const void* src) {
    asm volatile("cp.async.cg.shared.global [%0], [%1], 16;" :: "r"(dst), "l"(src) : "memory");
}
#define CP_COMMIT() asm volatile("cp.async.commit_group;" ::: "memory")
#define CP_WAIT0()  asm volatile("cp.async.wait_group 0;" ::: "memory")

// ---------------------------------------------------------------------------
// k_prep: zero masks + pre-split all operands to bf16 hi/lo tile layouts.
__global__ __launch_bounds__(256)
void k_prep(const float* __restrict__ C,
            const float* __restrict__ WL1, const float* __restrict__ WL2,
            const float* __restrict__ W1,  const float* __restrict__ W2) {
    int g = blockIdx.x * 256 + threadIdx.x;        // 0 .. 262143
    // C: [16384, 64] -> 128B rows
    {
        int row = g >> 4, q = g & 15;
        float4 v = ((const float4*)C)[g];
        uint2 hi, lo;
        split4(v, hi, lo);
        uint32_t off = (uint32_t)row * 128u + (((uint32_t)q * 8u) ^ (((uint32_t)row & 7u) << 4));
        *(uint2*)(g_Cs_hi + off) = hi;
        *(uint2*)(g_Cs_lo + off) = lo;
    }
    // W1: [512, 128] -> 4 chunks x (128 rows x 256B)
    if (g < 16384) {
        int row = g >> 5, q = g & 31;
        float4 v = ((const float4*)W1)[g];
        uint2 hi, lo;
        split4(v, hi, lo);
        int c = row >> 7, r = row & 127;
        uint32_t off = (uint32_t)c * 32768u + (uint32_t)r * 256u +
                       (((uint32_t)q * 8u) ^ (((uint32_t)r & 7u) << 4));
        *(uint2*)(g_W1s_hi + off) = hi;
        *(uint2*)(g_W1s_lo + off) = lo;
    }
    // W2: [64, 512] -> 4 chunks x (64 rows x 256B)
    if (g < 8192) {
        int row = g >> 7, q = g & 127;
        float4 v = ((const float4*)W2)[g];
        uint2 hi, lo;
        split4(v, hi, lo);
        int c = q >> 5, qq = q & 31;
        uint32_t off = (uint32_t)c * 16384u + (uint32_t)row * 256u +
                       (((uint32_t)qq * 8u) ^ (((uint32_t)row & 7u) << 4));
        *(uint2*)(g_W2s_hi + off) = hi;
        *(uint2*)(g_W2s_lo + off) = lo;
    }
    // W_L1 / W_L2: [64, 64] -> 128B rows; order: L1hi, L1lo, L2hi, L2lo
    if (g < 2048) {
        int w = g >> 10, ii = g & 1023;
        int r = ii >> 4, q = ii & 15;
        float4 v = ((const float4*)(w ? WL2 : WL1))[ii];
        uint2 hi, lo;
        split4(v, hi, lo);
        uint32_t off = (uint32_t)r * 128u + (((uint32_t)q * 8u) ^ (((uint32_t)r & 7u) << 4));
        uint32_t base = (uint32_t)w * 16384u;
        *(uint2*)(g_Wxy + base + off)         = hi;
        *(uint2*)(g_Wxy + base + 8192u + off) = lo;
    }
    // zero masks (1024 uint4 total)
    if (g < 1024) {
        if (g < 512) ((uint4*)g_Mb)[g]        = make_uint4(0, 0, 0, 0);
        else         ((uint4*)g_MTb)[g - 512] = make_uint4(0, 0, 0, 0);
    }
}

// ---------------------------------------------------------------------------
// k_xy: edge scatter + (X = C@W1^T, Y = C@W2^T) via mma.sync bf16x3.
#define XY_CHI  0u
#define XY_CLO  16384u
#define XY_WBASE 32768u
#define XY_W1HI 32768u
#define XY_W1LO 40960u
#define XY_W2HI 49152u
#define XY_W2LO 57344u
#define XY_SMEM 65536u

__global__ __launch_bounds__(256, 1)
void k_xy(const int* __restrict__ ei, int E) {
    extern __shared__ char smem[];
    uint32_t sb = smem_u32(smem);
    int tid = threadIdx.x;
    int wid = tid >> 5, lane = tid & 31;
    int e0 = blockIdx.x * 128;
    int rw = wid * 16;

    // issue async staging: C tile + all 4 weight slabs (pure copies)
    #pragma unroll
    for (int i = 0; i < 8; i++) {
        int idx = tid + i * 256;                  // 0..2047
        int buf = idx >> 10, ii = idx & 1023;
        int r = ii >> 3, sgm = ii & 7;
        const char* src = (buf ? g_Cs_lo : g_Cs_hi) + (size_t)(e0 + r) * 128 + sgm * 16;
        cpasync16(sb + (buf ? XY_CLO : XY_CHI) + (uint32_t)r * 128u + (uint32_t)sgm * 16u, src);
    }
    #pragma unroll
    for (int i = 0; i < 8; i++) {
        int idx = tid + i * 256;                  // 0..2047
        cpasync16(sb + XY_WBASE + (uint32_t)idx * 16u, g_Wxy + (size_t)idx * 16);
    }
    CP_COMMIT();

    // scatter (overlaps the async copies)
    {
        int g = blockIdx.x * 256 + tid;
        if (g < E) {
            int i = ei[g];
            int k = ei[E + g];
            g_M16 [i * NNODES + k] = (unsigned short)g;
            g_MT16[k * NNODES + i] = (unsigned short)g;
            atomicOr(&g_Mb [i * 16 + (k >> 5)], 1u << (k & 31));
            atomicOr(&g_MTb[k * 16 + (i >> 5)], 1u << (i & 31));
        }
    }
    CP_WAIT0();
    __syncthreads();

    int l7 = lane & 7;
    int sel = lane >> 3;
    uint32_t xorv = (uint32_t)l7 << 4;
    uint32_t aRow = (uint32_t)(rw + (sel & 1) * 8 + l7) * 128u;
    uint32_t aKof = (uint32_t)(sel >> 1) * 16u;
    uint32_t bRow = (uint32_t)((sel >> 1) * 8 + l7) * 128u;
    uint32_t bKof = (uint32_t)(sel & 1) * 16u;

    float dX[8][4], dY[8][4];
    #pragma unroll
    for (int i = 0; i < 8; i++)
        #pragma unroll
        for (int j = 0; j < 4; j++) { dX[i][j] = 0.f; dY[i][j] = 0.f; }

    #pragma unroll
    for (int ks = 0; ks < 4; ks++) {
        uint32_t kb = (uint32_t)ks * 32u;
        uint32_t ch[4], cl[4];
        ldmx4(ch, sb + XY_CHI + aRow + ((kb + aKof) ^ xorv));
        ldmx4(cl, sb + XY_CLO + aRow + ((kb + aKof) ^ xorv));
        #pragma unroll
        for (int np = 0; np < 4; np++) {
            uint32_t off = (uint32_t)np * 2048u + bRow + ((kb + bKof) ^ xorv);
            uint32_t b1h[4], b1l[4], b2h[4], b2l[4];
            ldmx4(b1h, sb + XY_W1HI + off);
            ldmx4(b1l, sb + XY_W1LO + off);
            ldmx4(b2h, sb + XY_W2HI + off);
            ldmx4(b2l, sb + XY_W2LO + off);
            mma16816(dX[2 * np],     ch, b1h[0], b1h[1]);
            mma16816(dX[2 * np + 1], ch, b1h[2], b1h[3]);
            mma16816(dX[2 * np],     ch, b1l[0], b1l[1]);
            mma16816(dX[2 * np + 1], ch, b1l[2], b1l[3]);
            mma16816(dX[2 * np],     cl, b1h[0], b1h[1]);
            mma16816(dX[2 * np + 1], cl, b1h[2], b1h[3]);
            mma16816(dY[2 * np],     ch, b2h[0], b2h[1]);
            mma16816(dY[2 * np + 1], ch, b2h[2], b2h[3]);
            mma16816(dY[2 * np],     ch, b2l[0], b2l[1]);
            mma16816(dY[2 * np + 1], ch, b2l[2], b2l[3]);
            mma16816(dY[2 * np],     cl, b2h[0], b2h[1]);
            mma16816(dY[2 * np + 1], cl, b2h[2], b2h[3]);
        }
    }

    int r0 = e0 + rw + (lane >> 2);
    int c0 = (lane & 3) * 2;
    #pragma unroll
    for (int nt = 0; nt < 8; nt++) {
        *(float2*)(g_X + (size_t)r0 * 64 + nt * 8 + c0)       = make_float2(dX[nt][0], dX[nt][1]);
        *(float2*)(g_X + (size_t)(r0 + 8) * 64 + nt * 8 + c0) = make_float2(dX[nt][2], dX[nt][3]);
        *(float2*)(g_Y + (size_t)r0 * 64 + nt * 8 + c0)       = make_float2(dY[nt][0], dY[nt][1]);
        *(float2*)(g_Y + (size_t)(r0 + 8) * 64 + nt * 8 + c0) = make_float2(dY[nt][2], dY[nt][3]);
    }
}

// ---------------------------------------------------------------------------
// k_mlp: fused path-contraction + MLP, software-pipelined staging.
#define OFF_AHI   0u
#define OFF_ALO   32768u
#define OFF_B1HI  65536u
#define OFF_B1LO  98304u
#define OFF_B2    131072u                       // 2 buffers x (16KB hi + 16KB lo)
#define OFF_PAIRS 196608u
#define OFF_CNT   (OFF_PAIRS + 128u * PMAX * 4u)
#define OFF_EI    (OFF_CNT + 512u)
#define SMEM_TOT  (OFF_EI + 1024u)

__device__ __forceinline__ void stage_B1(uint32_t sb, int c, int tid) {
    #pragma unroll
    for (int i = 0; i < 16; i++) {
        int idx = tid + i * 256;                 // 0..4095
        int buf = idx >> 11, ii = idx & 2047;
        const char* src = (buf ? g_W1s_lo : g_W1s_hi) + (size_t)c * 32768 + (size_t)ii * 16;
        cpasync16(sb + OFF_B1HI + (uint32_t)buf * 32768u + (uint32_t)ii * 16u, src);
    }
}
__device__ __forceinline__ void stage_B2(uint32_t sb, int c, int b, int tid) {
    #pragma unroll
    for (int i = 0; i < 8; i++) {
        int idx = tid + i * 256;                 // 0..2047
        int buf = idx >> 10, ii = idx & 1023;
        const char* src = (buf ? g_W2s_lo : g_W2s_hi) + (size_t)c * 16384 + (size_t)ii * 16;
        cpasync16(sb + OFF_B2 + (uint32_t)b * 32768u + (uint32_t)buf * 16384u + (uint32_t)ii * 16u, src);
    }
}

__global__ __launch_bounds__(256, 1)
void k_mlp(const int* __restrict__ ei, float* __restrict__ out, int E) {
    extern __shared__ char smem[];
    uint32_t sb = smem_u32(smem);
    uint32_t* s_pairs = (uint32_t*)(smem + OFF_PAIRS);
    int*      s_cnt   = (int*)(smem + OFF_CNT);
    int*      s_ei    = (int*)(smem + OFF_EI);
    int tid = threadIdx.x;
    int wid = tid >> 5, lane = tid & 31;
    int e0 = blockIdx.x * 128;
    int rw = wid * 16;

    // prologue: edge endpoints + zero counts
    if (tid < 128) s_ei[tid] = ei[e0 + tid];
    else           s_ei[tid] = ei[E + e0 + tid - 128];
    if (lane < 16) s_cnt[rw + lane] = 0;

    // prefetch A-left (C), B1 chunk 0, B2 chunk 0 (buffer 0)
    #pragma unroll
    for (int i = 0; i < 8; i++) {
        int idx = tid + i * 256;
        int buf = idx >> 10, ii = idx & 1023;
        int r = ii >> 3, sgm = ii & 7;
        const char* src = (buf ? g_Cs_lo : g_Cs_hi) + (size_t)(e0 + r) * 128 + sgm * 16;
        cpasync16(sb + (buf ? OFF_ALO : OFF_AHI) + (uint32_t)r * 256u + (uint32_t)sgm * 16u, src);
    }
    stage_B1(sb, 0, tid);
    stage_B2(sb, 0, 0, tid);
    CP_COMMIT();
    __syncthreads();                            // s_ei / s_cnt visible

    // phase 1: pair extraction (2 threads per edge; overlaps async copies)
    {
        int le = tid >> 1;
        int i = s_ei[le], k = s_ei[128 + le];
        int wb = (tid & 1) * 8;
        const uint32_t* mb  = &g_Mb [i * 16 + wb];
        const uint32_t* mtb = &g_MTb[k * 16 + wb];
        #pragma unroll
        for (int w8 = 0; w8 < 8; w8++) {
            uint32_t m = mb[w8] & mtb[w8];
            while (m) {
                int b = __ffs(m) - 1;
                m &= m - 1;
                int j = (wb + w8) * 32 + b;
                uint32_t e1 = g_M16 [i * NNODES + j];
                uint32_t e2 = g_MT16[k * NNODES + j];
                int p = atomicAdd(&s_cnt[le], 1);
                if (p < PMAX) s_pairs[le * PMAX + p] = e1 | (e2 << 16);
            }
        }
    }
    __syncwarp();

    // phase 2: path products -> A cols 64..127 (2-edge interleave)
    {
        const float2* Xb = (const float2*)g_X;
        const float2* Yb = (const float2*)g_Y;
        for (int t = 0; t < 16; t += 2) {
            int le0 = rw + t, le1 = rw + t + 1;
            int n0 = s_cnt[le0]; n0 = n0 < PMAX ? n0 : PMAX;
            int n1 = s_cnt[le1]; n1 = n1 < PMAX ? n1 : PMAX;
            float2 a0 = make_float2(0.f, 0.f), a1 = make_float2(0.f, 0.f);
            int nm = n0 > n1 ? n0 : n1;
            for (int p = 0; p < nm; p += 2) {
                #pragma unroll
                for (int j = 0; j < 2; j++) {
                    if (p + j < n0) {
                        uint32_t pr = s_pairs[le0 * PMAX + p + j];
                        float2 x = Xb[(size_t)(pr & 0xffffu) * 32 + lane];
                        float2 y = Yb[(size_t)(pr >> 16) * 32 + lane];
                        a0.x = fmaf(x.x, y.x, a0.x);
                        a0.y = fmaf(x.y, y.y, a0.y);
                    }
                    if (p + j < n1) {
                        uint32_t pr = s_pairs[le1 * PMAX + p + j];
                        float2 x = Xb[(size_t)(pr & 0xffffu) * 32 + lane];
                        float2 y = Yb[(size_t)(pr >> 16) * 32 + lane];
                        a1.x = fmaf(x.x, y.x, a1.x);
                        a1.y = fmaf(x.y, y.y, a1.y);
                    }
                }
            }
            #pragma unroll
            for (int j = 0; j < 2; j++) {
                float2 acc = j ? a1 : a0;
                int le = j ? le1 : le0;
                __nv_bfloat16 h0 = __float2bfloat16(acc.x), h1 = __float2bfloat16(acc.y);
                uint32_t hi = packbf(__bfloat162float(h0), __bfloat162float(h1));
                uint32_t lo = packbf(acc.x - __bfloat162float(h0), acc.y - __bfloat162float(h1));
                uint32_t kb = 128u + (uint32_t)lane * 4u;
                uint32_t phys = (uint32_t)le * 256u + (kb ^ (((uint32_t)le & 7u) << 4));
                *(uint32_t*)(smem + OFF_AHI + phys) = hi;
                *(uint32_t*)(smem + OFF_ALO + phys) = lo;
            }
        }
    }
    CP_WAIT0();
    __syncthreads();

    // main loop
    int l7 = lane & 7;
    int sel = lane >> 3;
    uint32_t xorv = (uint32_t)l7 << 4;
    uint32_t aRow = (uint32_t)(rw + (sel & 1) * 8 + l7) * 256u;
    uint32_t aKof = (uint32_t)(sel >> 1) * 16u;
    uint32_t bRowBase = (uint32_t)((sel >> 1) * 8 + l7) * 256u;
    uint32_t bKof = (uint32_t)(sel & 1) * 16u;

    float d2a[8][4];
    #pragma unroll
    for (int i = 0; i < 8; i++)
        #pragma unroll
        for (int j = 0; j < 4; j++) d2a[i][j] = 0.f;

    for (int c = 0; c < 4; c++) {
        float d1[16][4];
        #pragma unroll
        for (int i = 0; i < 16; i++)
            #pragma unroll
            for (int j = 0; j < 4; j++) d1[i][j] = 0.f;

        // MMA1: d1 += A @ B1^T (bf16x3)
        #pragma unroll
        for (int ks = 0; ks < 8; ks++) {
            uint32_t kb = (uint32_t)ks * 32u;
            uint32_t ah[4], al[4];
            ldmx4(ah, sb + OFF_AHI + aRow + ((kb + aKof) ^ xorv));
            ldmx4(al, sb + OFF_ALO + aRow + ((kb + aKof) ^ xorv));
            #pragma unroll
            for (int np = 0; np < 8; np++) {
                uint32_t off = (uint32_t)np * 4096u + bRowBase + ((kb + bKof) ^ xorv);
                uint32_t bh[4], bl[4];
                ldmx4(bh, sb + OFF_B1HI + off);
                ldmx4(bl, sb + OFF_B1LO + off);
                mma16816(d1[2 * np],     ah, bh[0], bh[1]);
                mma16816(d1[2 * np + 1], ah, bh[2], bh[3]);
                mma16816(d1[2 * np],     ah, bl[0], bl[1]);
                mma16816(d1[2 * np + 1], ah, bl[2], bl[3]);
                mma16816(d1[2 * np],     al, bh[0], bh[1]);
                mma16816(d1[2 * np + 1], al, bh[2], bh[3]);
            }
        }

        __syncthreads();            // all B1 reads done
        if (c < 3) {
            stage_B1(sb, c + 1, tid);
            stage_B2(sb, c + 1, (c + 1) & 1, tid);
            CP_COMMIT();
        }

        // MMA2: d2a += relu(d1) @ B2^T   (B2 buffer c&1; overlaps prefetch)
        uint32_t b2h_base = sb + OFF_B2 + (uint32_t)(c & 1) * 32768u;
        uint32_t b2l_base = b2h_base + 16384u;
        #pragma unroll
        for (int kt = 0; kt < 8; kt++) {
            float va0 = fmaxf(d1[2 * kt][0], 0.f), va1 = fmaxf(d1[2 * kt][1], 0.f);
            float va2 = fmaxf(d1[2 * kt][2], 0.f), va3 = fmaxf(d1[2 * kt][3], 0.f);
            float vb0 = fmaxf(d1[2 * kt + 1][0], 0.f), vb1 = fmaxf(d1[2 * kt + 1][1], 0.f);
            float vb2 = fmaxf(d1[2 * kt + 1][2], 0.f), vb3 = fmaxf(d1[2 * kt + 1][3], 0.f);
            float ha0 = __bfloat162float(__float2bfloat16(va0));
            float ha1 = __bfloat162float(__float2bfloat16(va1));
            float ha2 = __bfloat162float(__float2bfloat16(va2));
            float ha3 = __bfloat162float(__float2bfloat16(va3));
            float hb0 = __bfloat162float(__float2bfloat16(vb0));
            float hb1 = __bfloat162float(__float2bfloat16(vb1));
            float hb2 = __bfloat162float(__float2bfloat16(vb2));
            float hb3 = __bfloat162float(__float2bfloat16(vb3));
            uint32_t ah[4] = { packbf(ha0, ha1), packbf(ha2, ha3),
                               packbf(hb0, hb1), packbf(hb2, hb3) };
            uint32_t al[4] = { packbf(va0 - ha0, va1 - ha1), packbf(va2 - ha2, va3 - ha3),
                               packbf(vb0 - hb0, vb1 - hb1), packbf(vb2 - hb2, vb3 - hb3) };
            uint32_t kb = (uint32_t)kt * 32u;
            #pragma unroll
            for (int np = 0; np < 4; np++) {
                uint32_t bh[4], bl[4];
                uint32_t off = (uint32_t)np * 4096u + bRowBase + ((kb + bKof) ^ xorv);
                ldmx4(bh, b2h_base + off);
                ldmx4(bl, b2l_base + off);
                mma16816(d2a[2 * np],     ah, bh[0], bh[1]);
                mma16816(d2a[2 * np + 1], ah, bh[2], bh[3]);
                mma16816(d2a[2 * np],     ah, bl[0], bl[1]);
                mma16816(d2a[2 * np + 1], ah, bl[2], bl[3]);
                mma16816(d2a[2 * np],     al, bh[0], bh[1]);
                mma16816(d2a[2 * np + 1], al, bh[2], bh[3]);
            }
        }
        if (c < 3) { CP_WAIT0(); __syncthreads(); }
    }

    int r0 = e0 + rw + (lane >> 2);
    int c0 = (lane & 3) * 2;
    #pragma unroll
    for (int nt = 0; nt < 8; nt++) {
        *(float2*)(out + (size_t)r0 * 64 + nt * 8 + c0)       = make_float2(d2a[nt][0], d2a[nt][1]);
        *(float2*)(out + (size_t)(r0 + 8) * 64 + nt * 8 + c0) = make_float2(d2a[nt][2], d2a[nt][3]);
    }
}

// ---------------------------------------------------------------------------
extern "C" void kernel_launch(void* const* d_in, const int* in_sizes, int n_in,
                              void* d_out, int out_size) {
    const int*   edge_index = (const int*)  d_in[0];   // [2, E]
    const float* C          = (const float*)d_in[1];   // [E, 64]
    const float* W_L1       = (const float*)d_in[3];   // [64, 64]
    const float* W_L2       = (const float*)d_in[4];   // [64, 64]
    const float* W_mlp1     = (const float*)d_in[5];   // [512, 128]
    const float* W_mlp2     = (const float*)d_in[6];   // [64, 512]
    float* out = (float*)d_out;                        // [E, 64]

    int E = in_sizes[0] / 2;                           // 16384

    k_prep<<<1024, 256>>>(C, W_L1, W_L2, W_mlp1, W_mlp2);

    cudaFuncSetAttribute(k_xy, cudaFuncAttributeMaxDynamicSharedMemorySize, XY_SMEM);
    k_xy<<<E / 128, 256, XY_SMEM>>>(edge_index, E);

    cudaFuncSetAttribute(k_mlp, cudaFuncAttributeMaxDynamicSharedMemorySize, SMEM_TOT);
    k_mlp<<<E / 128, 256, SMEM_TOT>>>(edge_index, out, E);
}